// round 1
// baseline (speedup 1.0000x reference)
#include <cuda_runtime.h>
#include <math.h>

#define H 1024
#define V 50257
#define L 12

// ---------------- scratch (no allocs allowed) ----------------
__device__ float g_embedded[H];
__device__ float g_attn_applied[H];
__device__ float g_x[H];
__device__ float g_hnew[H];
__device__ float g_logits[V];
__device__ float g_stats[2];   // [0]=max, [1]=log(sumexp)

// ---------------- Kernel A: embed gather + attention ----------------
// 1 block, 384 threads (12 warps; warp j computes attention logit j).
__global__ void kA(const int* __restrict__ tok,
                   const float* __restrict__ hidden,        // [H]
                   const float* __restrict__ enc,           // [L,H]
                   const float* __restrict__ emb,           // [V,H]
                   const float* __restrict__ attn_W,        // [L,2H]
                   const float* __restrict__ attn_b,        // [L]
                   float* __restrict__ out_attnw)           // d_out + V + H
{
    __shared__ float s_w[L];
    const int t = threadIdx.x;
    const int wid = t >> 5, lane = t & 31;
    const int token = tok[0];
    const float* __restrict__ erow = emb + (size_t)token * H;

    // gather embedded into scratch
    for (int i = t; i < H; i += 384) g_embedded[i] = erow[i];

    // attention logit for row wid (12 warps, one row each)
    {
        const float* __restrict__ wrow = attn_W + wid * (2 * H);
        float s = 0.f;
        #pragma unroll 4
        for (int k = lane; k < H; k += 32) s += erow[k] * wrow[k];
        #pragma unroll 4
        for (int k = lane; k < H; k += 32) s += hidden[k] * wrow[H + k];
        #pragma unroll
        for (int o = 16; o; o >>= 1) s += __shfl_xor_sync(0xffffffffu, s, o);
        if (lane == 0) s_w[wid] = s + attn_b[wid];
    }
    __syncthreads();

    // softmax over L=12 (thread 0)
    if (t == 0) {
        float m = s_w[0];
        #pragma unroll
        for (int j = 1; j < L; j++) m = fmaxf(m, s_w[j]);
        float sum = 0.f;
        #pragma unroll
        for (int j = 0; j < L; j++) { float e = expf(s_w[j] - m); s_w[j] = e; sum += e; }
        float inv = 1.f / sum;
        #pragma unroll
        for (int j = 0; j < L; j++) s_w[j] *= inv;
    }
    __syncthreads();

    // attn_applied[i] = sum_j w[j] * enc[j][i]
    for (int i = t; i < H; i += 384) {
        float a = 0.f;
        #pragma unroll
        for (int j = 0; j < L; j++) a = fmaf(s_w[j], enc[j * H + i], a);
        g_attn_applied[i] = a;
    }
    if (t < L) out_attnw[t] = s_w[t];
}

// ---------------- Kernel B: x = relu(comb_W @ [embedded; attn_applied] + b) ----
// warp per row; grid 128 x 256 threads
__global__ void kB(const float* __restrict__ comb_W,   // [H, 2H]
                   const float* __restrict__ comb_b)   // [H]
{
    const int wid = threadIdx.x >> 5, lane = threadIdx.x & 31;
    const int row = blockIdx.x * 8 + wid;
    const float4* __restrict__ w = (const float4*)(comb_W + (size_t)row * (2 * H));
    const float4* __restrict__ ve = (const float4*)g_embedded;
    const float4* __restrict__ va = (const float4*)g_attn_applied;

    float s = 0.f;
    #pragma unroll
    for (int k = lane; k < 256; k += 32) {           // first half: embedded
        float4 wv = w[k]; float4 xv = ve[k];
        s = fmaf(wv.x, xv.x, fmaf(wv.y, xv.y, fmaf(wv.z, xv.z, fmaf(wv.w, xv.w, s))));
    }
    #pragma unroll
    for (int k = lane; k < 256; k += 32) {           // second half: attn_applied
        float4 wv = w[256 + k]; float4 xv = va[k];
        s = fmaf(wv.x, xv.x, fmaf(wv.y, xv.y, fmaf(wv.z, xv.z, fmaf(wv.w, xv.w, s))));
    }
    #pragma unroll
    for (int o = 16; o; o >>= 1) s += __shfl_xor_sync(0xffffffffu, s, o);
    if (lane == 0) g_x[row] = fmaxf(s + comb_b[row], 0.f);
}

// ---------------- Kernel C: h_new = tanh(Wih@x + bih + Whh@h0 + bhh) ----------
__global__ void kC(const float* __restrict__ Wih,
                   const float* __restrict__ Whh,
                   const float* __restrict__ bih,
                   const float* __restrict__ bhh,
                   const float* __restrict__ hidden,   // h0 [H]
                   float* __restrict__ out_h)          // d_out + V
{
    const int wid = threadIdx.x >> 5, lane = threadIdx.x & 31;
    const int row = blockIdx.x * 8 + wid;
    const float4* __restrict__ wi = (const float4*)(Wih + (size_t)row * H);
    const float4* __restrict__ wh = (const float4*)(Whh + (size_t)row * H);
    const float4* __restrict__ vx = (const float4*)g_x;
    const float4* __restrict__ vh = (const float4*)hidden;

    float s = 0.f;
    #pragma unroll
    for (int k = lane; k < 256; k += 32) {
        float4 wv = wi[k]; float4 xv = vx[k];
        s = fmaf(wv.x, xv.x, fmaf(wv.y, xv.y, fmaf(wv.z, xv.z, fmaf(wv.w, xv.w, s))));
    }
    #pragma unroll
    for (int k = lane; k < 256; k += 32) {
        float4 wv = wh[k]; float4 xv = vh[k];
        s = fmaf(wv.x, xv.x, fmaf(wv.y, xv.y, fmaf(wv.z, xv.z, fmaf(wv.w, xv.w, s))));
    }
    #pragma unroll
    for (int o = 16; o; o >>= 1) s += __shfl_xor_sync(0xffffffffu, s, o);
    if (lane == 0) {
        float h = tanhf(s + bih[row] + bhh[row]);
        g_hnew[row] = h;
        out_h[row] = h;
    }
}

// ---------------- Kernel D1: logits = out_W @ h_new + out_b (the big one) -----
// warp per row, h_new staged in shared (float4), 8 rows/block.
__global__ __launch_bounds__(256) void kD1(const float* __restrict__ out_W,
                                           const float* __restrict__ out_b)
{
    __shared__ float4 s_h[256];
    s_h[threadIdx.x] = ((const float4*)g_hnew)[threadIdx.x];
    __syncthreads();

    const int wid = threadIdx.x >> 5, lane = threadIdx.x & 31;
    const int row = blockIdx.x * 8 + wid;
    if (row >= V) return;

    const float4* __restrict__ w = (const float4*)(out_W + (size_t)row * H);
    float s = 0.f;
    #pragma unroll
    for (int k = 0; k < 8; k++) {
        float4 wv = w[k * 32 + lane];
        float4 hv = s_h[k * 32 + lane];
        s = fmaf(wv.x, hv.x, fmaf(wv.y, hv.y, fmaf(wv.z, hv.z, fmaf(wv.w, hv.w, s))));
    }
    #pragma unroll
    for (int o = 16; o; o >>= 1) s += __shfl_xor_sync(0xffffffffu, s, o);
    if (lane == 0) g_logits[row] = s + out_b[row];
}

// ---------------- Kernel D2: single block — max + log-sum-exp over V ----------
__global__ __launch_bounds__(1024) void kD2()
{
    __shared__ float red[32];
    const int t = threadIdx.x, lane = t & 31, wid = t >> 5;

    float m = -INFINITY;
    for (int i = t; i < V; i += 1024) m = fmaxf(m, g_logits[i]);
    #pragma unroll
    for (int o = 16; o; o >>= 1) m = fmaxf(m, __shfl_xor_sync(0xffffffffu, m, o));
    if (lane == 0) red[wid] = m;
    __syncthreads();
    float M = red[lane & 31];
    if (wid == 0) {
        #pragma unroll
        for (int o = 16; o; o >>= 1) M = fmaxf(M, __shfl_xor_sync(0xffffffffu, M, o));
        if (lane == 0) red[0] = M;
    }
    __syncthreads();
    M = red[0];
    __syncthreads();

    float s = 0.f;
    for (int i = t; i < V; i += 1024) s += expf(g_logits[i] - M);
    #pragma unroll
    for (int o = 16; o; o >>= 1) s += __shfl_xor_sync(0xffffffffu, s, o);
    __shared__ float red2[32];
    if (lane == 0) red2[wid] = s;
    __syncthreads();
    if (wid == 0) {
        float S = red2[lane];
        #pragma unroll
        for (int o = 16; o; o >>= 1) S += __shfl_xor_sync(0xffffffffu, S, o);
        if (lane == 0) { g_stats[0] = M; g_stats[1] = logf(S); }
    }
}

// ---------------- Kernel D3: logp = logits - max - logZ -----------------------
__global__ void kD3(float* __restrict__ out_logp)
{
    const float c = g_stats[0] + g_stats[1];
    for (int i = blockIdx.x * blockDim.x + threadIdx.x; i < V; i += gridDim.x * blockDim.x)
        out_logp[i] = g_logits[i] - c;
}

// ---------------- launcher ----------------------------------------------------
extern "C" void kernel_launch(void* const* d_in, const int* in_sizes, int n_in,
                              void* d_out, int out_size)
{
    const int*   tok    = (const int*)  d_in[0];
    const float* hidden = (const float*)d_in[1];
    const float* enc    = (const float*)d_in[2];
    const float* emb    = (const float*)d_in[3];
    const float* attn_W = (const float*)d_in[4];
    const float* attn_b = (const float*)d_in[5];
    const float* comb_W = (const float*)d_in[6];
    const float* comb_b = (const float*)d_in[7];
    const float* Wih    = (const float*)d_in[8];
    const float* Whh    = (const float*)d_in[9];
    const float* bih    = (const float*)d_in[10];
    const float* bhh    = (const float*)d_in[11];
    const float* out_W  = (const float*)d_in[12];
    const float* out_b  = (const float*)d_in[13];

    float* out = (float*)d_out;
    float* out_logp  = out;           // [V]
    float* out_h     = out + V;       // [H]
    float* out_attnw = out + V + H;   // [L]

    kA<<<1, 384>>>(tok, hidden, enc, emb, attn_W, attn_b, out_attnw);
    kB<<<H / 8, 256>>>(comb_W, comb_b);
    kC<<<H / 8, 256>>>(Wih, Whh, bih, bhh, hidden, out_h);
    kD1<<<(V + 7) / 8, 256>>>(out_W, out_b);
    kD2<<<1, 1024>>>();
    kD3<<<160, 256>>>(out_logp);
}

// round 2
// speedup vs baseline: 1.2340x; 1.2340x over previous
#include <cuda_runtime.h>
#include <math.h>

#define H 1024
#define V 50257
#define L 12
#define NB 148                 // persistent blocks (<= SM count, all co-resident)
#define NT 1024
#define NWARP (NB * 32)        // 4736 global warps

// ---------------- scratch (no allocs allowed) ----------------
__device__ float g_attn_logit[L];
__device__ float g_x[H];
__device__ float g_hnew[H];
__device__ __align__(16) float g_logits[V];
__device__ float g_part_m[NB];
__device__ float g_part_s[NB];

// software grid barrier state
__device__ unsigned g_bar_arrive = 0;
__device__ volatile unsigned g_bar_gen = 0;

__device__ __forceinline__ void grid_barrier()
{
    __syncthreads();
    if (threadIdx.x == 0) {
        __threadfence();
        unsigned gen = g_bar_gen;                 // read BEFORE arriving
        unsigned t = atomicAdd(&g_bar_arrive, 1u);
        if (t == NB - 1) {
            g_bar_arrive = 0;
            __threadfence();
            g_bar_gen = gen + 1;                  // release
        } else {
            while (g_bar_gen == gen) { }          // spin on L2 (volatile)
            __threadfence();
        }
    }
    __syncthreads();
}

__device__ __forceinline__ float warp_sum(float v)
{
    #pragma unroll
    for (int o = 16; o; o >>= 1) v += __shfl_xor_sync(0xffffffffu, v, o);
    return v;
}

__global__ __launch_bounds__(NT, 1) void fused(
    const int*   __restrict__ tok,
    const float* __restrict__ hidden,     // [H]
    const float* __restrict__ enc,        // [L,H]
    const float* __restrict__ emb,        // [V,H]
    const float* __restrict__ attn_W,     // [L,2H]
    const float* __restrict__ attn_b,     // [L]
    const float* __restrict__ comb_W,     // [H,2H]
    const float* __restrict__ comb_b,     // [H]
    const float* __restrict__ Wih,        // [H,H]
    const float* __restrict__ Whh,        // [H,H]
    const float* __restrict__ bih,        // [H]
    const float* __restrict__ bhh,        // [H]
    const float* __restrict__ out_W,      // [V,H]
    const float* __restrict__ out_b,      // [V]
    float* __restrict__ out_logp,         // [V]
    float* __restrict__ out_h,            // [H]
    float* __restrict__ out_attnw)        // [L]
{
    const int tid  = threadIdx.x;
    const int bid  = blockIdx.x;
    const int lane = tid & 31;
    const int wid  = tid >> 5;
    const int gw   = bid * 32 + wid;      // global warp id

    __shared__ float sh_red[32];
    __shared__ float sh_red2[32];
    __shared__ __align__(16) float sh_vecA[H];
    __shared__ __align__(16) float sh_vecB[H];
    __shared__ float sh_c;

    const int token = tok[0];
    const float* __restrict__ erow = emb + (size_t)token * H;

    // ---------- Phase A1: attention logits (blocks 0..11, one row each) ----------
    if (bid < L) {
        const float* __restrict__ wrow = attn_W + bid * (2 * H);
        float p = erow[tid] * wrow[tid] + hidden[tid] * wrow[H + tid];
        p = warp_sum(p);
        if (lane == 0) sh_red[wid] = p;
        __syncthreads();
        if (wid == 0) {
            float v = sh_red[lane];
            v = warp_sum(v);
            if (lane == 0) g_attn_logit[bid] = v + attn_b[bid];
        }
    }
    grid_barrier();

    // ---------- Phase A2: redundant softmax + stage [embedded ; attn_applied] ----
    float aw[L];
    {
        float m = -INFINITY;
        #pragma unroll
        for (int j = 0; j < L; j++) { aw[j] = g_attn_logit[j]; m = fmaxf(m, aw[j]); }
        float sum = 0.f;
        #pragma unroll
        for (int j = 0; j < L; j++) { aw[j] = expf(aw[j] - m); sum += aw[j]; }
        float inv = 1.f / sum;
        #pragma unroll
        for (int j = 0; j < L; j++) aw[j] *= inv;
    }
    if (bid == 0 && tid < L) out_attnw[tid] = aw[tid];

    sh_vecA[tid] = erow[tid];
    {
        float a = 0.f;
        #pragma unroll
        for (int j = 0; j < L; j++) a = fmaf(aw[j], enc[j * H + tid], a);
        sh_vecB[tid] = a;
    }
    __syncthreads();

    // ---------- Phase B: x = relu(comb_W @ [e;a] + b)  (warps 0..1023) ----------
    if (gw < H) {
        const float4* __restrict__ wr = (const float4*)(comb_W + (size_t)gw * (2 * H));
        const float4* ve = (const float4*)sh_vecA;
        const float4* va = (const float4*)sh_vecB;
        float s = 0.f;
        #pragma unroll
        for (int k = 0; k < 8; k++) {
            float4 wv = wr[k * 32 + lane];
            float4 xv = ve[k * 32 + lane];
            s = fmaf(wv.x, xv.x, fmaf(wv.y, xv.y, fmaf(wv.z, xv.z, fmaf(wv.w, xv.w, s))));
        }
        #pragma unroll
        for (int k = 0; k < 8; k++) {
            float4 wv = wr[256 + k * 32 + lane];
            float4 xv = va[k * 32 + lane];
            s = fmaf(wv.x, xv.x, fmaf(wv.y, xv.y, fmaf(wv.z, xv.z, fmaf(wv.w, xv.w, s))));
        }
        s = warp_sum(s);
        if (lane == 0) g_x[gw] = fmaxf(s + comb_b[gw], 0.f);
    }
    grid_barrier();

    // ---------- Phase C: h_new = tanh(Wih@x + Whh@h0 + b)  (warps 0..1023) -------
    sh_vecA[tid] = g_x[tid];
    sh_vecB[tid] = hidden[tid];
    __syncthreads();
    if (gw < H) {
        const float4* __restrict__ wi = (const float4*)(Wih + (size_t)gw * H);
        const float4* __restrict__ wh = (const float4*)(Whh + (size_t)gw * H);
        const float4* vx = (const float4*)sh_vecA;
        const float4* vh = (const float4*)sh_vecB;
        float s = 0.f;
        #pragma unroll
        for (int k = 0; k < 8; k++) {
            float4 wv = wi[k * 32 + lane];
            float4 xv = vx[k * 32 + lane];
            s = fmaf(wv.x, xv.x, fmaf(wv.y, xv.y, fmaf(wv.z, xv.z, fmaf(wv.w, xv.w, s))));
        }
        #pragma unroll
        for (int k = 0; k < 8; k++) {
            float4 wv = wh[k * 32 + lane];
            float4 xv = vh[k * 32 + lane];
            s = fmaf(wv.x, xv.x, fmaf(wv.y, xv.y, fmaf(wv.z, xv.z, fmaf(wv.w, xv.w, s))));
        }
        s = warp_sum(s);
        if (lane == 0) {
            float h = tanhf(s + bih[gw] + bhh[gw]);
            g_hnew[gw] = h;
            out_h[gw]  = h;
        }
    }
    grid_barrier();

    // ---------- Phase D1: logits + online log-sum-exp (all 4736 warps) ----------
    sh_vecA[tid] = g_hnew[tid];
    __syncthreads();
    const float4* h4 = (const float4*)sh_vecA;

    float m = -INFINITY, ssum = 0.f;
    for (int row = gw; row < V; row += NWARP) {
        const float4* __restrict__ wr = (const float4*)(out_W + (size_t)row * H);
        float acc = 0.f;
        #pragma unroll
        for (int k = 0; k < 8; k++) {
            float4 wv = wr[k * 32 + lane];
            float4 hv = h4[k * 32 + lane];
            acc = fmaf(wv.x, hv.x, fmaf(wv.y, hv.y, fmaf(wv.z, hv.z, fmaf(wv.w, hv.w, acc))));
        }
        acc = warp_sum(acc);                       // all lanes hold the dot
        float logit = acc + out_b[row];
        if (lane == 0) g_logits[row] = logit;
        float nm = fmaxf(m, logit);
        ssum = ssum * expf(m - nm) + expf(logit - nm);
        m = nm;
    }
    // block combine (32 warp partials)
    if (lane == 0) { sh_red[wid] = m; sh_red2[wid] = ssum; }
    __syncthreads();
    if (wid == 0) {
        float bm = sh_red[lane], bs = sh_red2[lane];
        #pragma unroll
        for (int o = 16; o; o >>= 1) {
            float om = __shfl_xor_sync(0xffffffffu, bm, o);
            float os = __shfl_xor_sync(0xffffffffu, bs, o);
            float nm = fmaxf(bm, om);
            bs = bs * expf(bm - nm) + os * expf(om - nm);
            bm = nm;
        }
        if (lane == 0) { g_part_m[bid] = bm; g_part_s[bid] = bs; }
    }
    grid_barrier();

    // ---------- Phase D2: redundant final reduce over 148 partials ----------
    if (wid == 0) {
        float bm = -INFINITY, bs = 0.f;
        for (int i = lane; i < NB; i += 32) {
            float pm = g_part_m[i], ps = g_part_s[i];
            float nm = fmaxf(bm, pm);
            bs = bs * expf(bm - nm) + ps * expf(pm - nm);
            bm = nm;
        }
        #pragma unroll
        for (int o = 16; o; o >>= 1) {
            float om = __shfl_xor_sync(0xffffffffu, bm, o);
            float os = __shfl_xor_sync(0xffffffffu, bs, o);
            float nm = fmaxf(bm, om);
            bs = bs * expf(bm - nm) + os * expf(om - nm);
            bm = nm;
        }
        if (lane == 0) sh_c = bm + logf(bs);
    }
    __syncthreads();
    const float c = sh_c;

    // ---------- Phase D3: logp = logits - c  (coalesced float4) ----------
    {
        const float4* lg4 = (const float4*)g_logits;
        float4* o4 = (float4*)out_logp;
        int i = bid * NT + tid;                  // V/4 = 12564.25
        if (i < 12564) {
            float4 v = lg4[i];
            v.x -= c; v.y -= c; v.z -= c; v.w -= c;
            o4[i] = v;
        }
        if (i == 12564) out_logp[V - 1] = g_logits[V - 1] - c;
    }
}

// ---------------- launcher ----------------------------------------------------
extern "C" void kernel_launch(void* const* d_in, const int* in_sizes, int n_in,
                              void* d_out, int out_size)
{
    const int*   tok    = (const int*)  d_in[0];
    const float* hidden = (const float*)d_in[1];
    const float* enc    = (const float*)d_in[2];
    const float* emb    = (const float*)d_in[3];
    const float* attn_W = (const float*)d_in[4];
    const float* attn_b = (const float*)d_in[5];
    const float* comb_W = (const float*)d_in[6];
    const float* comb_b = (const float*)d_in[7];
    const float* Wih    = (const float*)d_in[8];
    const float* Whh    = (const float*)d_in[9];
    const float* bih    = (const float*)d_in[10];
    const float* bhh    = (const float*)d_in[11];
    const float* out_W  = (const float*)d_in[12];
    const float* out_b  = (const float*)d_in[13];

    float* out = (float*)d_out;
    fused<<<NB, NT>>>(tok, hidden, enc, emb, attn_W, attn_b,
                      comb_W, comb_b, Wih, Whh, bih, bhh, out_W, out_b,
                      out, out + V, out + V + H);
}

// round 3
// speedup vs baseline: 1.2402x; 1.0050x over previous
#include <cuda_runtime.h>
#include <math.h>

#define H 1024
#define V 50257
#define L 12
#define NB 148                 // persistent blocks, all co-resident
#define NT 1024
#define NWARP (NB * 32)        // 4736 global warps

// V = 4736*10 + 2897 ; float4 count = 12564 full + 1 scalar tail (elem 50256)
#define V4 12564
#define SLICE_S 340            // 148*340 >= V   (exp-sum slices)
#define SLICE_W 85             // 148*85  >= 12565 (write slices, float4)

// ---------------- scratch ----------------
__device__ float g_attn_logit[L];
__device__ float g_hh[H];                    // Whh @ h0
__device__ float g_x[H];
__device__ float g_hnew[H];
__device__ __align__(16) float g_logits[V];
__device__ float g_part_m[NB];
__device__ float g_part_s[NB];

__device__ unsigned g_bar_arrive = 0;
__device__ volatile unsigned g_bar_gen = 0;

__device__ __forceinline__ void grid_barrier()
{
    __syncthreads();
    if (threadIdx.x == 0) {
        __threadfence();
        unsigned gen = g_bar_gen;
        unsigned t = atomicAdd(&g_bar_arrive, 1u);
        if (t == NB - 1) {
            g_bar_arrive = 0;
            __threadfence();
            g_bar_gen = gen + 1;
        } else {
            while (g_bar_gen == gen) { }
            __threadfence();
        }
    }
    __syncthreads();
}

__device__ __forceinline__ float warp_sum(float v)
{
    #pragma unroll
    for (int o = 16; o; o >>= 1) v += __shfl_xor_sync(0xffffffffu, v, o);
    return v;
}
__device__ __forceinline__ float warp_max(float v)
{
    #pragma unroll
    for (int o = 16; o; o >>= 1) v = fmaxf(v, __shfl_xor_sync(0xffffffffu, v, o));
    return v;
}

// prefetch one 4KB weight row into L2 (lane covers its own 128B line)
__device__ __forceinline__ void prefetch_row(const float* rowp, int lane)
{
    asm volatile("prefetch.global.L2 [%0];" :: "l"(rowp + lane * 32));
}

__global__ __launch_bounds__(NT, 1) void fused(
    const int*   __restrict__ tok,
    const float* __restrict__ hidden,     // [H]
    const float* __restrict__ enc,        // [L,H]
    const float* __restrict__ emb,        // [V,H]
    const float* __restrict__ attn_W,     // [L,2H]
    const float* __restrict__ attn_b,     // [L]
    const float* __restrict__ comb_W,     // [H,2H]
    const float* __restrict__ comb_b,     // [H]
    const float* __restrict__ Wih,        // [H,H]
    const float* __restrict__ Whh,        // [H,H]
    const float* __restrict__ bih,        // [H]
    const float* __restrict__ bhh,        // [H]
    const float* __restrict__ out_W,      // [V,H]
    const float* __restrict__ out_b,      // [V]
    float* __restrict__ out_logp,         // [V]
    float* __restrict__ out_h,            // [H]
    float* __restrict__ out_attnw)        // [L]
{
    const int tid  = threadIdx.x;
    const int bid  = blockIdx.x;
    const int lane = tid & 31;
    const int wid  = tid >> 5;
    const int gw   = bid * 32 + wid;

    __shared__ float red[32];
    __shared__ __align__(16) float sA[H];
    __shared__ __align__(16) float sB[H];
    __shared__ float sh_M, sh_c;

    const int token = tok[0];
    const float* __restrict__ erow = emb + (size_t)token * H;

    // ================= P1: attention logits  ||  Whh @ h0  ||  prefetch =======
    if (bid < L) {
        // one attention logit per block: dot over 2H
        float p = erow[tid] * attn_W[bid * (2 * H) + tid]
                + hidden[tid] * attn_W[bid * (2 * H) + H + tid];
        p = warp_sum(p);
        if (lane == 0) red[wid] = p;
        __syncthreads();
        if (wid == 0) {
            float v = warp_sum(red[lane]);
            if (lane == 0) g_attn_logit[bid] = v + attn_b[bid];
        }
    } else if (bid >= 16 && bid < 48) {
        // Whh @ h0, warp-per-row
        sA[tid] = hidden[tid];
        __syncthreads();
        const int row = (bid - 16) * 32 + wid;
        const float4* __restrict__ wr = (const float4*)(Whh + (size_t)row * H);
        const float4* vh = (const float4*)sA;
        float s = 0.f;
        #pragma unroll
        for (int k = 0; k < 8; k++) {
            float4 wv = wr[k * 32 + lane];
            float4 xv = vh[k * 32 + lane];
            s = fmaf(wv.x, xv.x, fmaf(wv.y, xv.y, fmaf(wv.z, xv.z, fmaf(wv.w, xv.w, s))));
        }
        s = warp_sum(s);
        if (lane == 0) g_hh[row] = s;
    } else if (bid >= 48) {
        // prefetch this block's first-iteration out_W rows into L2
        prefetch_row(out_W + (size_t)gw * H, lane);
    }
    grid_barrier();

    // ================= P2: x = relu(comb_W @ [e;a] + b)  (blocks 0..31) =======
    if (bid < 32) {
        // redundant 12-way softmax
        float aw[L];
        float mm = -INFINITY;
        #pragma unroll
        for (int j = 0; j < L; j++) { aw[j] = g_attn_logit[j]; mm = fmaxf(mm, aw[j]); }
        float sum = 0.f;
        #pragma unroll
        for (int j = 0; j < L; j++) { aw[j] = expf(aw[j] - mm); sum += aw[j]; }
        float inv = 1.f / sum;
        #pragma unroll
        for (int j = 0; j < L; j++) aw[j] *= inv;
        if (bid == 0 && tid < L) out_attnw[tid] = aw[tid];

        sA[tid] = erow[tid];
        float a = 0.f;
        #pragma unroll
        for (int j = 0; j < L; j++) a = fmaf(aw[j], enc[j * H + tid], a);
        sB[tid] = a;
        __syncthreads();

        const int row = bid * 32 + wid;
        const float4* __restrict__ wr = (const float4*)(comb_W + (size_t)row * (2 * H));
        const float4* ve = (const float4*)sA;
        const float4* va = (const float4*)sB;
        float s = 0.f;
        #pragma unroll
        for (int k = 0; k < 8; k++) {
            float4 wv = wr[k * 32 + lane];
            float4 xv = ve[k * 32 + lane];
            s = fmaf(wv.x, xv.x, fmaf(wv.y, xv.y, fmaf(wv.z, xv.z, fmaf(wv.w, xv.w, s))));
        }
        #pragma unroll
        for (int k = 0; k < 8; k++) {
            float4 wv = wr[256 + k * 32 + lane];
            float4 xv = va[k * 32 + lane];
            s = fmaf(wv.x, xv.x, fmaf(wv.y, xv.y, fmaf(wv.z, xv.z, fmaf(wv.w, xv.w, s))));
        }
        s = warp_sum(s);
        if (lane == 0) g_x[row] = fmaxf(s + comb_b[row], 0.f);
    } else if (bid < 48) {
        prefetch_row(out_W + (size_t)gw * H, lane);
    }
    grid_barrier();

    // ================= P3: h_new = tanh(Wih@x + hh + b)  (blocks 32..63) ======
    if (bid >= 32 && bid < 64) {
        sA[tid] = g_x[tid];
        __syncthreads();
        const int row = (bid - 32) * 32 + wid;
        const float4* __restrict__ wr = (const float4*)(Wih + (size_t)row * H);
        const float4* vx = (const float4*)sA;
        float s = 0.f;
        #pragma unroll
        for (int k = 0; k < 8; k++) {
            float4 wv = wr[k * 32 + lane];
            float4 xv = vx[k * 32 + lane];
            s = fmaf(wv.x, xv.x, fmaf(wv.y, xv.y, fmaf(wv.z, xv.z, fmaf(wv.w, xv.w, s))));
        }
        s = warp_sum(s);
        if (lane == 0) {
            float h = tanhf(s + g_hh[row] + bih[row] + bhh[row]);
            g_hnew[row] = h;
            out_h[row]  = h;
        }
    } else if (bid < 32) {
        prefetch_row(out_W + (size_t)gw * H, lane);
    }
    grid_barrier();

    // ================= P4: logits GEMV + running max (all warps) ==============
    sA[tid] = g_hnew[tid];
    __syncthreads();
    {
        const float4* h4 = (const float4*)sA;
        float4 hr[8];
        #pragma unroll
        for (int k = 0; k < 8; k++) hr[k] = h4[k * 32 + lane];

        float m = -INFINITY;
        int row = gw;
        for (; row + NWARP < V; row += 2 * NWARP) {
            const float4* __restrict__ w0 = (const float4*)out_W + (size_t)row * 256 + lane;
            const float4* __restrict__ w1 = (const float4*)out_W + (size_t)(row + NWARP) * 256 + lane;
            float a0 = 0.f, a1 = 0.f;
            #pragma unroll
            for (int k = 0; k < 8; k++) {
                float4 v0 = w0[k * 32];
                float4 v1 = w1[k * 32];
                a0 = fmaf(v0.x, hr[k].x, fmaf(v0.y, hr[k].y, fmaf(v0.z, hr[k].z, fmaf(v0.w, hr[k].w, a0))));
                a1 = fmaf(v1.x, hr[k].x, fmaf(v1.y, hr[k].y, fmaf(v1.z, hr[k].z, fmaf(v1.w, hr[k].w, a1))));
            }
            #pragma unroll
            for (int o = 16; o; o >>= 1) {
                a0 += __shfl_xor_sync(0xffffffffu, a0, o);
                a1 += __shfl_xor_sync(0xffffffffu, a1, o);
            }
            float l0 = a0 + out_b[row];
            float l1 = a1 + out_b[row + NWARP];
            if (lane == 0) { g_logits[row] = l0; g_logits[row + NWARP] = l1; }
            m = fmaxf(m, fmaxf(l0, l1));
        }
        if (row < V) {
            const float4* __restrict__ w0 = (const float4*)out_W + (size_t)row * 256 + lane;
            float a0 = 0.f;
            #pragma unroll
            for (int k = 0; k < 8; k++) {
                float4 v0 = w0[k * 32];
                a0 = fmaf(v0.x, hr[k].x, fmaf(v0.y, hr[k].y, fmaf(v0.z, hr[k].z, fmaf(v0.w, hr[k].w, a0))));
            }
            a0 = warp_sum(a0);
            float l0 = a0 + out_b[row];
            if (lane == 0) g_logits[row] = l0;
            m = fmaxf(m, l0);
        }
        // block max
        m = warp_max(m);
        if (lane == 0) red[wid] = m;
        __syncthreads();
        if (wid == 0) {
            float bm = warp_max(red[lane]);
            if (lane == 0) g_part_m[bid] = bm;
        }
    }
    grid_barrier();

    // ================= P5: global max + per-block exp-sum slice ===============
    if (wid == 0) {
        float bm = -INFINITY;
        for (int i = lane; i < NB; i += 32) bm = fmaxf(bm, g_part_m[i]);
        bm = warp_max(bm);
        if (lane == 0) sh_M = bm;
    }
    __syncthreads();
    const float M = sh_M;
    {
        int i = bid * SLICE_S + tid;
        float e = (tid < SLICE_S && i < V) ? expf(g_logits[i] - M) : 0.f;
        e = warp_sum(e);
        if (lane == 0) red[wid] = e;
        __syncthreads();
        if (wid == 0) {
            float bs = warp_sum(red[lane]);
            if (lane == 0) g_part_s[bid] = bs;
        }
    }
    grid_barrier();

    // ================= P6: combine + write logp ===============================
    if (wid == 0) {
        float s = 0.f;
        for (int i = lane; i < NB; i += 32) s += g_part_s[i];
        s = warp_sum(s);
        if (lane == 0) sh_c = M + logf(s);
    }
    __syncthreads();
    const float c = sh_c;
    if (tid < SLICE_W) {
        int i4 = bid * SLICE_W + tid;
        if (i4 < V4) {
            float4 v = ((const float4*)g_logits)[i4];
            v.x -= c; v.y -= c; v.z -= c; v.w -= c;
            ((float4*)out_logp)[i4] = v;
        } else if (i4 == V4) {
            out_logp[V - 1] = g_logits[V - 1] - c;
        }
    }
}

// ---------------- launcher ----------------------------------------------------
extern "C" void kernel_launch(void* const* d_in, const int* in_sizes, int n_in,
                              void* d_out, int out_size)
{
    const int*   tok    = (const int*)  d_in[0];
    const float* hidden = (const float*)d_in[1];
    const float* enc    = (const float*)d_in[2];
    const float* emb    = (const float*)d_in[3];
    const float* attn_W = (const float*)d_in[4];
    const float* attn_b = (const float*)d_in[5];
    const float* comb_W = (const float*)d_in[6];
    const float* comb_b = (const float*)d_in[7];
    const float* Wih    = (const float*)d_in[8];
    const float* Whh    = (const float*)d_in[9];
    const float* bih    = (const float*)d_in[10];
    const float* bhh    = (const float*)d_in[11];
    const float* out_W  = (const float*)d_in[12];
    const float* out_b  = (const float*)d_in[13];

    float* out = (float*)d_out;
    fused<<<NB, NT>>>(tok, hidden, enc, emb, attn_W, attn_b,
                      comb_W, comb_b, Wih, Whh, bih, bhh, out_W, out_b,
                      out, out + V, out + V + H);
}

// round 4
// speedup vs baseline: 1.2806x; 1.0326x over previous
#include <cuda_runtime.h>
#include <math.h>

#define H 1024
#define V 50257
#define L 12
#define NB 148                 // persistent blocks, all co-resident
#define NT 1024
#define NWARP (NB * 32)        // 4736 global warps

#define V4 12564               // full float4's in V (tail elem 50256)
#define SLICE_S 340            // 148*340 >= V  (LSE slices)
#define SLICE_W 85             // 148*85  >= 12565 (write slices, float4)

// ---------------- scratch ----------------
__device__ float g_attn_logit[L];
__device__ __align__(16) float g_hhp[4096];   // Whh@h0 partials (4 per row)
__device__ __align__(16) float g_xp[4096];    // comb partials
__device__ __align__(16) float g_ihp[4096];   // Wih@x partials
__device__ __align__(16) float g_logits[V];
__device__ float g_sm[NB];
__device__ float g_ss[NB];

__device__ unsigned g_bar_arrive = 0;
__device__ volatile unsigned g_bar_gen = 0;

__device__ __forceinline__ void grid_barrier()
{
    __syncthreads();
    if (threadIdx.x == 0) {
        __threadfence();
        unsigned gen = g_bar_gen;
        unsigned t = atomicAdd(&g_bar_arrive, 1u);
        if (t == NB - 1) {
            g_bar_arrive = 0;
            __threadfence();
            g_bar_gen = gen + 1;
        } else {
            while (g_bar_gen == gen) { }
            __threadfence();
        }
    }
    __syncthreads();
}

__device__ __forceinline__ float warp_sum(float v)
{
    #pragma unroll
    for (int o = 16; o; o >>= 1) v += __shfl_xor_sync(0xffffffffu, v, o);
    return v;
}
__device__ __forceinline__ float warp_max(float v)
{
    #pragma unroll
    for (int o = 16; o; o >>= 1) v = fmaxf(v, __shfl_xor_sync(0xffffffffu, v, o));
    return v;
}

__device__ __forceinline__ void prefetch_row(const float* rowp, int lane)
{
    asm volatile("prefetch.global.L2 [%0];" :: "l"(rowp + lane * 32));
}

__global__ __launch_bounds__(NT, 1) void fused(
    const int*   __restrict__ tok,
    const float* __restrict__ hidden,     // [H]
    const float* __restrict__ enc,        // [L,H]
    const float* __restrict__ emb,        // [V,H]
    const float* __restrict__ attn_W,     // [L,2H]
    const float* __restrict__ attn_b,     // [L]
    const float* __restrict__ comb_W,     // [H,2H]
    const float* __restrict__ comb_b,     // [H]
    const float* __restrict__ Wih,        // [H,H]
    const float* __restrict__ Whh,        // [H,H]
    const float* __restrict__ bih,        // [H]
    const float* __restrict__ bhh,        // [H]
    const float* __restrict__ out_W,      // [V,H]
    const float* __restrict__ out_b,      // [V]
    float* __restrict__ out_logp,         // [V]
    float* __restrict__ out_h,            // [H]
    float* __restrict__ out_attnw)        // [L]
{
    const int tid  = threadIdx.x;
    const int bid  = blockIdx.x;
    const int lane = tid & 31;
    const int wid  = tid >> 5;
    const int gw   = bid * 32 + wid;

    __shared__ float red[32];
    __shared__ __align__(16) float sA[H];
    __shared__ __align__(16) float sB[H];
    __shared__ float sh_M, sh_c;

    const int token = tok[0];
    const float* __restrict__ erow = emb + (size_t)token * H;

    // ======== P1: attention logits (blk 0..11) || Whh@h0 partials (blk 12..139) ====
    if (bid < L) {
        float p = erow[tid] * attn_W[bid * (2 * H) + tid]
                + hidden[tid] * attn_W[bid * (2 * H) + H + tid];
        p = warp_sum(p);
        if (lane == 0) red[wid] = p;
        __syncthreads();
        if (wid == 0) {
            float v = warp_sum(red[lane]);
            if (lane == 0) g_attn_logit[bid] = v + attn_b[bid];
        }
    } else if (bid < 140) {
        sA[tid] = hidden[tid];
        __syncthreads();
        const int lw  = gw - L * 32;            // 0..4095
        const int row = lw >> 2, q = lw & 3;    // 4-way K split (256 elems each)
        const float4* __restrict__ wr = (const float4*)Whh + (size_t)row * 256 + q * 64;
        const float4* vh = (const float4*)sA + q * 64;
        float s = 0.f;
        #pragma unroll
        for (int k = 0; k < 2; k++) {
            float4 wv = wr[k * 32 + lane];
            float4 xv = vh[k * 32 + lane];
            s = fmaf(wv.x, xv.x, fmaf(wv.y, xv.y, fmaf(wv.z, xv.z, fmaf(wv.w, xv.w, s))));
        }
        s = warp_sum(s);
        if (lane == 0) g_hhp[lw] = s;
    } else {
        prefetch_row(out_W + (size_t)gw * H, lane);
    }
    grid_barrier();

    // ======== P2: comb partials (blk 0..127, 4-way K split over [e;a]) =============
    if (bid < 128) {
        float aw[L];
        float mm = -INFINITY;
        #pragma unroll
        for (int j = 0; j < L; j++) { aw[j] = g_attn_logit[j]; mm = fmaxf(mm, aw[j]); }
        float sum = 0.f;
        #pragma unroll
        for (int j = 0; j < L; j++) { aw[j] = expf(aw[j] - mm); sum += aw[j]; }
        float inv = 1.f / sum;
        #pragma unroll
        for (int j = 0; j < L; j++) aw[j] *= inv;
        if (bid == 0 && tid < L) out_attnw[tid] = aw[tid];

        sA[tid] = erow[tid];
        float a = 0.f;
        #pragma unroll
        for (int j = 0; j < L; j++) a = fmaf(aw[j], enc[j * H + tid], a);
        sB[tid] = a;
        __syncthreads();

        const int row = gw >> 2, q = gw & 3;    // 512-elem K segment
        const float4* __restrict__ wr = (const float4*)comb_W + (size_t)row * 512 + q * 128;
        const float4* vv = ((q < 2) ? (const float4*)sA : (const float4*)sB) + (q & 1) * 128;
        float s = 0.f;
        #pragma unroll
        for (int k = 0; k < 4; k++) {
            float4 wv = wr[k * 32 + lane];
            float4 xv = vv[k * 32 + lane];
            s = fmaf(wv.x, xv.x, fmaf(wv.y, xv.y, fmaf(wv.z, xv.z, fmaf(wv.w, xv.w, s))));
        }
        s = warp_sum(s);
        if (lane == 0) g_xp[gw] = s;
    } else {
        prefetch_row(out_W + (size_t)(gw + NWARP) * H, lane);
    }
    grid_barrier();

    // ======== P3: x = relu(combine) redundant; Wih@x partials (blk 0..127) ========
    if (bid < 128) {
        float4 xp = ((const float4*)g_xp)[tid];
        sA[tid] = fmaxf(xp.x + xp.y + xp.z + xp.w + comb_b[tid], 0.f);
        __syncthreads();

        const int row = gw >> 2, q = gw & 3;
        const float4* __restrict__ wr = (const float4*)Wih + (size_t)row * 256 + q * 64;
        const float4* vx = (const float4*)sA + q * 64;
        float s = 0.f;
        #pragma unroll
        for (int k = 0; k < 2; k++) {
            float4 wv = wr[k * 32 + lane];
            float4 xv = vx[k * 32 + lane];
            s = fmaf(wv.x, xv.x, fmaf(wv.y, xv.y, fmaf(wv.z, xv.z, fmaf(wv.w, xv.w, s))));
        }
        s = warp_sum(s);
        if (lane == 0) g_ihp[gw] = s;
    }
    grid_barrier();

    // ======== P4: h_new combine (redundant per block) + logits GEMV ===============
    {
        float4 ih = ((const float4*)g_ihp)[tid];
        float4 hh = ((const float4*)g_hhp)[tid];
        float h = tanhf(ih.x + ih.y + ih.z + ih.w +
                        hh.x + hh.y + hh.z + hh.w + bih[tid] + bhh[tid]);
        sA[tid] = h;
        if (bid == 0) out_h[tid] = h;
    }
    __syncthreads();
    {
        const float4* h4 = (const float4*)sA;
        float4 hr[8];
        #pragma unroll
        for (int k = 0; k < 8; k++) hr[k] = h4[k * 32 + lane];

        int row = gw;
        for (; row + NWARP < V; row += 2 * NWARP) {
            const float4* __restrict__ w0 = (const float4*)out_W + (size_t)row * 256 + lane;
            const float4* __restrict__ w1 = (const float4*)out_W + (size_t)(row + NWARP) * 256 + lane;
            float a0 = 0.f, a1 = 0.f;
            #pragma unroll
            for (int k = 0; k < 8; k++) {
                float4 v0 = w0[k * 32];
                float4 v1 = w1[k * 32];
                a0 = fmaf(v0.x, hr[k].x, fmaf(v0.y, hr[k].y, fmaf(v0.z, hr[k].z, fmaf(v0.w, hr[k].w, a0))));
                a1 = fmaf(v1.x, hr[k].x, fmaf(v1.y, hr[k].y, fmaf(v1.z, hr[k].z, fmaf(v1.w, hr[k].w, a1))));
            }
            #pragma unroll
            for (int o = 16; o; o >>= 1) {
                a0 += __shfl_xor_sync(0xffffffffu, a0, o);
                a1 += __shfl_xor_sync(0xffffffffu, a1, o);
            }
            if (lane == 0) {
                g_logits[row]         = a0 + out_b[row];
                g_logits[row + NWARP] = a1 + out_b[row + NWARP];
            }
        }
        if (row < V) {
            const float4* __restrict__ w0 = (const float4*)out_W + (size_t)row * 256 + lane;
            float a0 = 0.f;
            #pragma unroll
            for (int k = 0; k < 8; k++) {
                float4 v0 = w0[k * 32];
                a0 = fmaf(v0.x, hr[k].x, fmaf(v0.y, hr[k].y, fmaf(v0.z, hr[k].z, fmaf(v0.w, hr[k].w, a0))));
            }
            a0 = warp_sum(a0);
            if (lane == 0) g_logits[row] = a0 + out_b[row];
        }
    }
    grid_barrier();

    // ======== P5: per-slice (max, expsum) — no dependence on global max ===========
    {
        const int i = bid * SLICE_S + tid;
        const bool ok = (tid < SLICE_S) && (i < V);
        float v = ok ? g_logits[i] : -INFINITY;
        float m = warp_max(v);
        if (lane == 0) red[wid] = m;
        __syncthreads();
        if (wid == 0) {
            float bm = warp_max(red[lane]);
            if (lane == 0) sh_M = bm;
        }
        __syncthreads();
        const float M = sh_M;
        float e = ok ? expf(v - M) : 0.f;
        e = warp_sum(e);
        __syncthreads();               // protect red[] reuse
        if (lane == 0) red[wid] = e;
        __syncthreads();
        if (wid == 0) {
            float bs = warp_sum(red[lane]);
            if (lane == 0) { g_sm[bid] = M; g_ss[bid] = bs; }
        }
    }
    grid_barrier();

    // ======== P6: redundant LSE merge of 148 pairs + write logp ===================
    if (wid == 0) {
        float bm = -INFINITY, bs = 0.f;
        for (int i = lane; i < NB; i += 32) {
            float pm = g_sm[i], ps = g_ss[i];
            float nm = fmaxf(bm, pm);
            bs = bs * expf(bm - nm) + ps * expf(pm - nm);
            bm = nm;
        }
        #pragma unroll
        for (int o = 16; o; o >>= 1) {
            float om = __shfl_xor_sync(0xffffffffu, bm, o);
            float os = __shfl_xor_sync(0xffffffffu, bs, o);
            float nm = fmaxf(bm, om);
            bs = bs * expf(bm - nm) + os * expf(om - nm);
            bm = nm;
        }
        if (lane == 0) sh_c = bm + logf(bs);
    }
    __syncthreads();
    const float c = sh_c;
    if (tid < SLICE_W) {
        int i4 = bid * SLICE_W + tid;
        if (i4 < V4) {
            float4 v = ((const float4*)g_logits)[i4];
            v.x -= c; v.y -= c; v.z -= c; v.w -= c;
            ((float4*)out_logp)[i4] = v;
        } else if (i4 == V4) {
            out_logp[V - 1] = g_logits[V - 1] - c;
        }
    }
}

// ---------------- launcher ----------------------------------------------------
extern "C" void kernel_launch(void* const* d_in, const int* in_sizes, int n_in,
                              void* d_out, int out_size)
{
    const int*   tok    = (const int*)  d_in[0];
    const float* hidden = (const float*)d_in[1];
    const float* enc    = (const float*)d_in[2];
    const float* emb    = (const float*)d_in[3];
    const float* attn_W = (const float*)d_in[4];
    const float* attn_b = (const float*)d_in[5];
    const float* comb_W = (const float*)d_in[6];
    const float* comb_b = (const float*)d_in[7];
    const float* Wih    = (const float*)d_in[8];
    const float* Whh    = (const float*)d_in[9];
    const float* bih    = (const float*)d_in[10];
    const float* bhh    = (const float*)d_in[11];
    const float* out_W  = (const float*)d_in[12];
    const float* out_b  = (const float*)d_in[13];

    float* out = (float*)d_out;
    fused<<<NB, NT>>>(tok, hidden, enc, emb, attn_W, attn_b,
                      comb_W, comb_b, Wih, Whh, bih, bhh, out_W, out_b,
                      out, out + V, out + V + H);
}